// round 9
// baseline (speedup 1.0000x reference)
#include <cuda_runtime.h>
#include <math.h>

#define S1 589824   // 768*768
#define S2 147456   // 384*384
#define S3 36864    // 192*192
#define NPOS 9216   // 96*96

// padded pitched buffers: interior origin (row 1, col 4)
#define P1 776
#define R1 770
#define CH1 (770*776)
#define P2 392
#define R2 386
#define CH2 (386*392)

__device__ float  g_f1p[16 * CH1];
__device__ float  g_f2p[32 * CH2];
__device__ float  g_f3[64 * S3];
__device__ double2 g_sp1[16 * 1152];
__device__ double2 g_sp2[32 * 576];
__device__ double2 g_sp3[64 * 288];
__device__ float  g_mean[3][64];
__device__ float  g_rstd[3][64];
__device__ float  g_heads[6][NPOS];
__device__ float  g_tr[NPOS * 6];

// ---- packed f32x2 helpers (FFMA2) ----
__device__ __forceinline__ unsigned long long pk2(float lo, float hi) {
    unsigned long long r;
    asm("mov.b64 %0, {%1, %2};" : "=l"(r) : "f"(lo), "f"(hi));
    return r;
}
__device__ __forceinline__ void fma2(unsigned long long& acc, unsigned long long a, unsigned long long b) {
    asm("fma.rn.f32x2 %0, %1, %2, %3;" : "=l"(acc) : "l"(a), "l"(b), "l"(acc));
}
__device__ __forceinline__ float2 unpk(unsigned long long v) {
    float2 f;
    asm("mov.b64 {%0, %1}, %2;" : "=f"(f.x), "=f"(f.y) : "l"(v));
    return f;
}
__device__ __forceinline__ void wred2(double& s, double& q) {
#pragma unroll
    for (int off = 16; off; off >>= 1) {
        s += __shfl_down_sync(0xffffffffu, s, off);
        q += __shfl_down_sync(0xffffffffu, q, off);
    }
}

// ---------------- conv1: 1 -> 16, 3x3, s1, p1; FFMA2; z-split; fused stats ----------------
__global__ void __launch_bounds__(128) k_conv1(const float* __restrict__ img, const float* __restrict__ w) {
    __shared__ float2 sW2[4 * 9];
    __shared__ double sRed[8][4], qRed[8][4];
    int tid = threadIdx.x;
    int z = blockIdx.z;
    if (tid < 36) {
        int pr = tid / 9, k = tid % 9;
        int oc0 = z * 8 + 2 * pr;
        sW2[tid] = make_float2(w[oc0 * 9 + k], w[(oc0 + 1) * 9 + k]);
    }
    __syncthreads();
    int xg = tid & 31, y = tid >> 5;
    int x0 = blockIdx.x * 128 + 4 * xg;
    int yy = blockIdx.y * 4 + y;
    unsigned long long acc[16];
#pragma unroll
    for (int i = 0; i < 16; i++) acc[i] = 0ull;
#pragma unroll
    for (int ky = 0; ky < 3; ky++) {
        int gy = yy + ky - 1;
        float v[6];
        if (gy >= 0 && gy < 768) {
            float4 a = *(const float4*)&img[gy * 768 + x0];
            v[1] = a.x; v[2] = a.y; v[3] = a.z; v[4] = a.w;
            v[0] = (x0 - 1 >= 0) ? img[gy * 768 + x0 - 1] : 0.f;
            v[5] = (x0 + 4 < 768) ? img[gy * 768 + x0 + 4] : 0.f;
        } else {
#pragma unroll
            for (int c = 0; c < 6; c++) v[c] = 0.f;
        }
        unsigned long long pk[6];
#pragma unroll
        for (int j = 0; j < 6; j++) pk[j] = pk2(v[j], v[j]);
#pragma unroll
        for (int p = 0; p < 4; p++) {
            float2 w0 = sW2[p * 9 + ky * 3 + 0];
            float2 w1 = sW2[p * 9 + ky * 3 + 1];
            float2 w2 = sW2[p * 9 + ky * 3 + 2];
            unsigned long long W0 = pk2(w0.x, w0.y), W1 = pk2(w1.x, w1.y), W2 = pk2(w2.x, w2.y);
#pragma unroll
            for (int px = 0; px < 4; px++) {
                fma2(acc[p * 4 + px], pk[px], W0);
                fma2(acc[p * 4 + px], pk[px + 1], W1);
                fma2(acc[p * 4 + px], pk[px + 2], W2);
            }
        }
    }
    double sC[8], qC[8];
#pragma unroll
    for (int p = 0; p < 4; p++) {
        float2 u0 = unpk(acc[p * 4 + 0]), u1 = unpk(acc[p * 4 + 1]);
        float2 u2 = unpk(acc[p * 4 + 2]), u3 = unpk(acc[p * 4 + 3]);
        int oc0 = z * 8 + 2 * p;
        size_t base = (size_t)(1 + yy) * P1 + 4 + x0;
        *(float4*)&g_f1p[oc0 * CH1 + base] = make_float4(u0.x, u1.x, u2.x, u3.x);
        *(float4*)&g_f1p[(oc0 + 1) * CH1 + base] = make_float4(u0.y, u1.y, u2.y, u3.y);
        sC[2 * p]     = (double)u0.x + (double)u1.x + (double)u2.x + (double)u3.x;
        qC[2 * p]     = (double)u0.x * u0.x + (double)u1.x * u1.x + (double)u2.x * u2.x + (double)u3.x * u3.x;
        sC[2 * p + 1] = (double)u0.y + (double)u1.y + (double)u2.y + (double)u3.y;
        qC[2 * p + 1] = (double)u0.y * u0.y + (double)u1.y * u1.y + (double)u2.y * u2.y + (double)u3.y * u3.y;
    }
    int lane = tid & 31, wp = tid >> 5;
#pragma unroll
    for (int c = 0; c < 8; c++) {
        double s = sC[c], q = qC[c];
        wred2(s, q);
        if (lane == 0) { sRed[c][wp] = s; qRed[c][wp] = q; }
    }
    __syncthreads();
    if (tid < 8) {
        double s = sRed[tid][0] + sRed[tid][1] + sRed[tid][2] + sRed[tid][3];
        double q = qRed[tid][0] + qRed[tid][1] + qRed[tid][2] + qRed[tid][3];
        int oc = z * 8 + tid;
        g_sp1[oc * 1152 + blockIdx.y * 6 + blockIdx.x] = make_double2(s, q);
    }
}

// ---------------- fused stat finalize + parallel border fill ----------------
// grid (C, NSEG): every block reduces the tiny partial array; seg 0 writes stats;
// border fill split across segs
__global__ void k_redfb(int stage) {
    int ch = blockIdx.x, seg = blockIdx.y, nseg = gridDim.y, tid = threadIdx.x;
    const double2* sp; int NB, elems;
    if (stage == 0)      { sp = g_sp1 + ch * 1152; NB = 1152; elems = S1; }
    else if (stage == 1) { sp = g_sp2 + ch * 576;  NB = 576;  elems = S2; }
    else                 { sp = g_sp3 + ch * 288;  NB = 288;  elems = S3; }
    double s = 0.0, q = 0.0;
    for (int i = tid; i < NB; i += 256) { double2 v = sp[i]; s += v.x; q += v.y; }
    __shared__ double ss[256], sq[256];
    __shared__ float smean;
    ss[tid] = s; sq[tid] = q;
    __syncthreads();
    for (int o = 128; o > 0; o >>= 1) {
        if (tid < o) { ss[tid] += ss[tid + o]; sq[tid] += sq[tid + o]; }
        __syncthreads();
    }
    if (tid == 0) {
        double m = ss[0] / (double)elems;
        if (seg == 0) {
            double var = sq[0] / (double)elems - m * m;
            g_mean[stage][ch] = (float)m;
            g_rstd[stage][ch] = (float)(1.0 / sqrt(var + 1e-5));
        }
        smean = (float)m;
    }
    __syncthreads();
    if (stage == 2) return;
    float m = smean;
    float* base; int pitch, rows;
    if (stage == 0) { base = g_f1p + (size_t)ch * CH1; pitch = P1; rows = R1; }
    else            { base = g_f2p + (size_t)ch * CH2; pitch = P2; rows = R2; }
    float4 mv = make_float4(m, m, m, m);
    if (seg == 0)
        for (int i = tid * 4; i < pitch; i += 1024) *(float4*)(base + i) = mv;
    if (seg == nseg - 1)
        for (int i = tid * 4; i < pitch; i += 1024) *(float4*)(base + (size_t)(rows - 1) * pitch + i) = mv;
    for (int r = 1 + seg * 256 + tid; r < rows - 1; r += nseg * 256) {
        *(float4*)(base + (size_t)r * pitch) = mv;
        *(float4*)(base + (size_t)r * pitch + pitch - 4) = mv;
    }
}

// ---------------- conv2: 16 -> 32, 3x3, s2, p1; dup-smem; FFMA2; fused stats ------------
__global__ void __launch_bounds__(256) k_conv2(const float* __restrict__ w) {
    __shared__ float2 sW2[16 * 16 * 9];        // 18.4KB
    __shared__ float2 sIn2[2][17 * 68];        // dup tiles {v,v}, 18.5KB
    __shared__ float2 sMR[16];
    __shared__ double sRed[32][2], qRed[32][2];
    int tid = threadIdx.x;
    for (int i = tid; i < 2304; i += 256) {
        int ic = i / 144, r = i % 144, pr = r / 9, k = r % 9;
        int oc0 = 2 * pr;
        sW2[i] = make_float2(w[(oc0 * 16 + ic) * 9 + k], w[((oc0 + 1) * 16 + ic) * 9 + k]);
    }
    if (tid < 16) {
        float m = g_mean[0][tid], rs = g_rstd[0][tid];
        sMR[tid] = make_float2(rs, -m * rs);
    }
    int xg = tid & 7, y = (tid >> 3) & 7, ocg = tid >> 6;
    int ox0 = blockIdx.x * 32, oy0 = blockIdx.y * 8;
    int goff[5], soff[5];
#pragma unroll
    for (int j = 0; j < 5; j++) {
        int e = tid + j * 256;
        int r = e / 65, c = e % 65;
        goff[j] = (2 * oy0 + r) * P1 + 3 + 2 * ox0 + c;
        soff[j] = r * 68 + c;
    }
    float vals[5];
#pragma unroll
    for (int j = 0; j < 5; j++) if (tid + j * 256 < 1105) vals[j] = g_f1p[goff[j]];
    unsigned long long acc[16];
#pragma unroll
    for (int i = 0; i < 16; i++) acc[i] = 0ull;
    int r0 = 2 * y, c0 = 8 * xg;
    __syncthreads();
#pragma unroll 1
    for (int ic = 0; ic < 16; ic++) {
        float2 mr = sMR[ic];
        float2* buf = sIn2[ic & 1];
#pragma unroll
        for (int j = 0; j < 5; j++)
            if (tid + j * 256 < 1105) {
                float nv = fmaxf(fmaf(vals[j], mr.x, mr.y), 0.f);
                buf[soff[j]] = make_float2(nv, nv);
            }
        __syncthreads();
        if (ic < 15) {
            const float* srcn = g_f1p + (size_t)(ic + 1) * CH1;
#pragma unroll
            for (int j = 0; j < 5; j++) if (tid + j * 256 < 1105) vals[j] = srcn[goff[j]];
        }
        const float2* wbase = &sW2[(ic * 16 + ocg * 4) * 9];
#pragma unroll
        for (int ky = 0; ky < 3; ky++) {
            const float2* row = &buf[(r0 + ky) * 68 + c0];
            unsigned long long pk[9];
            longlong2 q0 = *(const longlong2*)(row + 0);
            longlong2 q1 = *(const longlong2*)(row + 2);
            longlong2 q2 = *(const longlong2*)(row + 4);
            longlong2 q3 = *(const longlong2*)(row + 6);
            pk[0] = (unsigned long long)q0.x; pk[1] = (unsigned long long)q0.y;
            pk[2] = (unsigned long long)q1.x; pk[3] = (unsigned long long)q1.y;
            pk[4] = (unsigned long long)q2.x; pk[5] = (unsigned long long)q2.y;
            pk[6] = (unsigned long long)q3.x; pk[7] = (unsigned long long)q3.y;
            pk[8] = *(const unsigned long long*)(row + 8);
#pragma unroll
            for (int p = 0; p < 4; p++) {
                float2 w0 = wbase[p * 9 + ky * 3 + 0];
                float2 w1 = wbase[p * 9 + ky * 3 + 1];
                float2 w2 = wbase[p * 9 + ky * 3 + 2];
                unsigned long long W0 = pk2(w0.x, w0.y), W1 = pk2(w1.x, w1.y), W2 = pk2(w2.x, w2.y);
#pragma unroll
                for (int px = 0; px < 4; px++) {
                    fma2(acc[p * 4 + px], pk[2 * px + 0], W0);
                    fma2(acc[p * 4 + px], pk[2 * px + 1], W1);
                    fma2(acc[p * 4 + px], pk[2 * px + 2], W2);
                }
            }
        }
    }
    int oy = oy0 + y, oxb = ox0 + 4 * xg;
    size_t obase = (size_t)(1 + oy) * P2 + 4 + oxb;
    double sC[8], qC[8];
#pragma unroll
    for (int p = 0; p < 4; p++) {
        float2 u0 = unpk(acc[p * 4 + 0]), u1 = unpk(acc[p * 4 + 1]);
        float2 u2 = unpk(acc[p * 4 + 2]), u3 = unpk(acc[p * 4 + 3]);
        int oc0 = ocg * 8 + 2 * p;
        *(float4*)&g_f2p[oc0 * CH2 + obase] = make_float4(u0.x, u1.x, u2.x, u3.x);
        *(float4*)&g_f2p[(oc0 + 1) * CH2 + obase] = make_float4(u0.y, u1.y, u2.y, u3.y);
        sC[2 * p]     = (double)u0.x + (double)u1.x + (double)u2.x + (double)u3.x;
        qC[2 * p]     = (double)u0.x * u0.x + (double)u1.x * u1.x + (double)u2.x * u2.x + (double)u3.x * u3.x;
        sC[2 * p + 1] = (double)u0.y + (double)u1.y + (double)u2.y + (double)u3.y;
        qC[2 * p + 1] = (double)u0.y * u0.y + (double)u1.y * u1.y + (double)u2.y * u2.y + (double)u3.y * u3.y;
    }
    int lane = tid & 31, wp = tid >> 5;
#pragma unroll
    for (int c = 0; c < 8; c++) {
        double s = sC[c], q = qC[c];
        wred2(s, q);
        if (lane == 0) { sRed[ocg * 8 + c][wp & 1] = s; qRed[ocg * 8 + c][wp & 1] = q; }
    }
    __syncthreads();
    if (tid < 32) {
        double s = sRed[tid][0] + sRed[tid][1];
        double q = qRed[tid][0] + qRed[tid][1];
        g_sp2[tid * 576 + blockIdx.y * 12 + blockIdx.x] = make_double2(s, q);
    }
}

// ---------------- conv3: 32 -> 64, 3x3, s2, p1; dup-smem; FFMA2; z-split; fused stats ----
__global__ void __launch_bounds__(128) k_conv3(const float* __restrict__ w) {
    __shared__ float2 sW2[32 * 16 * 9];        // 36.9KB
    __shared__ float2 sIn2[2][17 * 36];        // 9.8KB
    __shared__ float2 sMR[32];
    int tid = threadIdx.x;
    int z = blockIdx.z;
    for (int i = tid; i < 4608; i += 128) {
        int ic = i / 144, r = i % 144, pr = r / 9, k = r % 9;
        int oc0 = z * 32 + 2 * pr;
        sW2[i] = make_float2(w[(oc0 * 32 + ic) * 9 + k], w[((oc0 + 1) * 32 + ic) * 9 + k]);
    }
    if (tid < 32) {
        float m = g_mean[1][tid], rs = g_rstd[1][tid];
        sMR[tid] = make_float2(rs, -m * rs);
    }
    int xg = tid & 3, y = (tid >> 2) & 7, ocg = (tid >> 5) & 3;
    int ox0 = blockIdx.x * 16, oy0 = blockIdx.y * 8;
    int goff[5], soff[5];
#pragma unroll
    for (int j = 0; j < 5; j++) {
        int e = tid + j * 128;
        int r = e / 33, c = e % 33;
        goff[j] = (2 * oy0 + r) * P2 + 3 + 2 * ox0 + c;
        soff[j] = r * 36 + c;
    }
    float vals[5];
#pragma unroll
    for (int j = 0; j < 5; j++) if (tid + j * 128 < 561) vals[j] = g_f2p[goff[j]];
    unsigned long long acc[16];
#pragma unroll
    for (int i = 0; i < 16; i++) acc[i] = 0ull;
    int r0 = 2 * y, c0 = 8 * xg;
    __syncthreads();
#pragma unroll 1
    for (int ic = 0; ic < 32; ic++) {
        float2 mr = sMR[ic];
        float2* buf = sIn2[ic & 1];
#pragma unroll
        for (int j = 0; j < 5; j++)
            if (tid + j * 128 < 561) {
                float nv = fmaxf(fmaf(vals[j], mr.x, mr.y), 0.f);
                buf[soff[j]] = make_float2(nv, nv);
            }
        __syncthreads();
        if (ic < 31) {
            const float* srcn = g_f2p + (size_t)(ic + 1) * CH2;
#pragma unroll
            for (int j = 0; j < 5; j++) if (tid + j * 128 < 561) vals[j] = srcn[goff[j]];
        }
        const float2* wbase = &sW2[(ic * 16 + ocg * 4) * 9];
#pragma unroll
        for (int ky = 0; ky < 3; ky++) {
            const float2* row = &buf[(r0 + ky) * 36 + c0];
            unsigned long long pk[9];
            longlong2 q0 = *(const longlong2*)(row + 0);
            longlong2 q1 = *(const longlong2*)(row + 2);
            longlong2 q2 = *(const longlong2*)(row + 4);
            longlong2 q3 = *(const longlong2*)(row + 6);
            pk[0] = (unsigned long long)q0.x; pk[1] = (unsigned long long)q0.y;
            pk[2] = (unsigned long long)q1.x; pk[3] = (unsigned long long)q1.y;
            pk[4] = (unsigned long long)q2.x; pk[5] = (unsigned long long)q2.y;
            pk[6] = (unsigned long long)q3.x; pk[7] = (unsigned long long)q3.y;
            pk[8] = *(const unsigned long long*)(row + 8);
#pragma unroll
            for (int p = 0; p < 4; p++) {
                float2 w0 = wbase[p * 9 + ky * 3 + 0];
                float2 w1 = wbase[p * 9 + ky * 3 + 1];
                float2 w2 = wbase[p * 9 + ky * 3 + 2];
                unsigned long long W0 = pk2(w0.x, w0.y), W1 = pk2(w1.x, w1.y), W2 = pk2(w2.x, w2.y);
#pragma unroll
                for (int px = 0; px < 4; px++) {
                    fma2(acc[p * 4 + px], pk[2 * px + 0], W0);
                    fma2(acc[p * 4 + px], pk[2 * px + 1], W1);
                    fma2(acc[p * 4 + px], pk[2 * px + 2], W2);
                }
            }
        }
    }
    int oy = oy0 + y, oxb = ox0 + 4 * xg;
    double sC[8], qC[8];
#pragma unroll
    for (int p = 0; p < 4; p++) {
        float2 u0 = unpk(acc[p * 4 + 0]), u1 = unpk(acc[p * 4 + 1]);
        float2 u2 = unpk(acc[p * 4 + 2]), u3 = unpk(acc[p * 4 + 3]);
        int oc0 = z * 32 + ocg * 8 + 2 * p;
        *(float4*)&g_f3[oc0 * S3 + oy * 192 + oxb] = make_float4(u0.x, u1.x, u2.x, u3.x);
        *(float4*)&g_f3[(oc0 + 1) * S3 + oy * 192 + oxb] = make_float4(u0.y, u1.y, u2.y, u3.y);
        sC[2 * p]     = (double)u0.x + (double)u1.x + (double)u2.x + (double)u3.x;
        qC[2 * p]     = (double)u0.x * u0.x + (double)u1.x * u1.x + (double)u2.x * u2.x + (double)u3.x * u3.x;
        sC[2 * p + 1] = (double)u0.y + (double)u1.y + (double)u2.y + (double)u3.y;
        qC[2 * p + 1] = (double)u0.y * u0.y + (double)u1.y * u1.y + (double)u2.y * u2.y + (double)u3.y * u3.y;
    }
    int lane = tid & 31;
#pragma unroll
    for (int c = 0; c < 8; c++) {
        double s = sC[c], q = qC[c];
        wred2(s, q);
        if (lane == 0)
            g_sp3[(z * 32 + ocg * 8 + c) * 288 + blockIdx.y * 12 + blockIdx.x] = make_double2(s, q);
    }
}

// ---------------- heads ----------------
__global__ void k_heads(const float* __restrict__ pw, const float* __restrict__ pb,
                        const float* __restrict__ tw, const float* __restrict__ tb,
                        const float* __restrict__ shw, const float* __restrict__ shb,
                        const float* __restrict__ scw, const float* __restrict__ scb,
                        const float* __restrict__ tiw, const float* __restrict__ tib) {
    __shared__ float sw[1536];
    __shared__ float sb[6];
    int tid = threadIdx.x;
    for (int i = tid; i < 1536; i += 128) {
        int h = i / 256, r = i % 256;
        const float* s; int off = r;
        if (h == 0) s = pw;
        else if (h == 1) s = tw;
        else if (h == 2) s = shw;
        else if (h == 3) { s = shw; off = r + 256; }
        else if (h == 4) s = scw;
        else s = tiw;
        sw[i] = s[off];
    }
    if (tid == 0) { sb[0] = pb[0]; sb[1] = tb[0]; sb[2] = shb[0]; sb[3] = shb[1]; sb[4] = scb[0]; sb[5] = tib[0]; }
    __syncthreads();
    int n = blockIdx.x * 128 + tid;
    int y = n / 96, x = n % 96;
    float acc[6] = {0.f, 0.f, 0.f, 0.f, 0.f, 0.f};
#pragma unroll 4
    for (int ic = 0; ic < 64; ic++) {
        float m = g_mean[2][ic], rs = g_rstd[2][ic];
        int base = ic * S3 + (2 * y) * 192 + 2 * x;
        float v0 = (g_f3[base] - m) * rs;       v0 = v0 > 0.f ? v0 : 0.f;
        float v1 = (g_f3[base + 1] - m) * rs;   v1 = v1 > 0.f ? v1 : 0.f;
        float v2 = (g_f3[base + 192] - m) * rs; v2 = v2 > 0.f ? v2 : 0.f;
        float v3 = (g_f3[base + 193] - m) * rs; v3 = v3 > 0.f ? v3 : 0.f;
#pragma unroll
        for (int h = 0; h < 6; h++) {
            const float* ww = &sw[h * 256 + ic * 4];
            acc[h] += v0 * ww[0] + v1 * ww[1] + v2 * ww[2] + v3 * ww[3];
        }
    }
    g_heads[0][n] = 3.14159f * tanhf(acc[0] + sb[0]);
    g_heads[1][n] = 3.14159f * tanhf(acc[1] + sb[1]);
    g_heads[2][n] = 0.2f * tanhf(acc[2] + sb[2]);
    g_heads[3][n] = 0.2f * tanhf(acc[3] + sb[3]);
    float sc = 1.f + 0.25f * tanhf(acc[4] + sb[4]);
    g_heads[4][n] = fminf(fmaxf(sc, 0.8f), 1.25f);
    float ti = 1.f + 0.8f * tanhf(acc[5] + sb[5]);
    g_heads[5][n] = fminf(fmaxf(ti, 1.0f), 1.8f);
}

// ---------------- transform build + aff output ----------------
__global__ void k_transform(float* __restrict__ aff) {
    int n = blockIdx.x * 256 + threadIdx.x;
    if (n >= NPOS) return;
    float psi = g_heads[0][n], th = g_heads[1][n];
    const float* sf = &g_heads[2][0];
    float sx = sf[2 * n], sy = sf[2 * n + 1];
    float s = g_heads[4][n], t = g_heads[5][n];
    float cp = cosf(psi), sp = sinf(psi), ct = cosf(th), st = sinf(th);
    float a = t * ct, b = -t * st, c = st / t, d = ct / t;
    float A00 = s * (cp * a - sp * c), A01 = s * (cp * b - sp * d);
    float A10 = s * (sp * a + cp * c), A11 = s * (sp * b + cp * d);
    float* tr = &g_tr[n * 6];
    tr[0] = A00; tr[1] = A01; tr[2] = sx; tr[3] = A10; tr[4] = A11; tr[5] = sy;
    float* af = aff + (size_t)n * 6;
    af[0] = 32.f * A00; af[1] = 32.f * A01; af[2] = (float)(4 + 8 * (n % 96)) + 32.f * sx;
    af[3] = 32.f * A10; af[4] = 32.f * A11; af[5] = (float)(4 + 8 * (n / 96)) + 32.f * sy;
}

// ---------------- bilinear sampler: 4 consecutive samples/thread, float4 store ----------
__device__ __forceinline__ float samp(const float* __restrict__ img, int py, int px, int yy, int xx) {
    if ((unsigned)xx >= 144u || (unsigned)yy >= 144u) return 0.f;
    int r = py * 8 + yy - 68, c = px * 8 + xx - 68;
    if ((unsigned)r >= 768u || (unsigned)c >= 768u) return 0.f;
    return img[r * 768 + c];
}

__global__ void k_sample(const float* __restrict__ img, float* __restrict__ outp) {
    int n = blockIdx.x;
    __shared__ float tr[6];
    if (threadIdx.x < 6) tr[threadIdx.x] = g_tr[n * 6 + threadIdx.x];
    __syncthreads();
    int px = n % 96, py = n / 96;
    int t4 = threadIdx.x * 4;
    int h = t4 >> 5, w0 = t4 & 31;
    float Y = (h + 0.5f) * 0.0625f - 1.f;
    float o[4];
#pragma unroll
    for (int j = 0; j < 4; j++) {
        float X = (w0 + j + 0.5f) * 0.0625f - 1.f;
        float gx = (tr[0] * X + tr[1] * Y + tr[2]) * (1.f / 4.5f);
        float gy = (tr[3] * X + tr[4] * Y + tr[5]) * (1.f / 4.5f);
        float ix = gx * 72.f + 71.5f;
        float iy = gy * 72.f + 71.5f;
        float x0 = floorf(ix), y0 = floorf(iy);
        float wx = ix - x0, wy = iy - y0;
        int xi = (int)x0, yi = (int)y0;
        float v00 = samp(img, py, px, yi, xi);
        float v01 = samp(img, py, px, yi, xi + 1);
        float v10 = samp(img, py, px, yi + 1, xi);
        float v11 = samp(img, py, px, yi + 1, xi + 1);
        o[j] = (1.f - wy) * ((1.f - wx) * v00 + wx * v01) + wy * ((1.f - wx) * v10 + wx * v11);
    }
    *(float4*)&outp[(size_t)n * 1024 + t4] = make_float4(o[0], o[1], o[2], o[3]);
}

extern "C" void kernel_launch(void* const* d_in, const int* in_sizes, int n_in,
                              void* d_out, int out_size) {
    const float* img = (const float*)d_in[0];
    const float* w1 = (const float*)d_in[1];
    const float* w2 = (const float*)d_in[2];
    const float* w3 = (const float*)d_in[3];
    const float* pw = (const float*)d_in[4];  const float* pb = (const float*)d_in[5];
    const float* tw = (const float*)d_in[6];  const float* tb = (const float*)d_in[7];
    const float* shw = (const float*)d_in[8]; const float* shb = (const float*)d_in[9];
    const float* scw = (const float*)d_in[10]; const float* scb = (const float*)d_in[11];
    const float* tiw = (const float*)d_in[12]; const float* tib = (const float*)d_in[13];

    float* out = (float*)d_out;          // transformed: 9216*1*32*32 floats
    float* aff = out + 9216 * 1024;      // aff: 9216*2*3 floats

    k_conv1<<<dim3(6, 192, 2), 128>>>(img, w1);
    k_redfb<<<dim3(16, 8), 256>>>(0);
    k_conv2<<<dim3(12, 48), 256>>>(w2);
    k_redfb<<<dim3(32, 8), 256>>>(1);
    k_conv3<<<dim3(12, 24, 2), 128>>>(w3);
    k_redfb<<<dim3(64, 1), 256>>>(2);
    k_heads<<<72, 128>>>(pw, pb, tw, tb, shw, shb, scw, scb, tiw, tib);
    k_transform<<<36, 256>>>(aff);
    k_sample<<<NPOS, 256>>>(img, out);
}

// round 10
// speedup vs baseline: 1.4244x; 1.4244x over previous
#include <cuda_runtime.h>
#include <math.h>

#define S1 589824   // 768*768
#define S2 147456   // 384*384
#define S3 36864    // 192*192
#define NPOS 9216   // 96*96

// padded pitched buffers: interior origin (row 1, col 4)
#define P1 776
#define R1 770
#define CH1 (770*776)
#define P2 392
#define R2 386
#define CH2 (386*392)

__device__ float  g_f1p[16 * CH1];
__device__ float  g_f2p[32 * CH2];
__device__ float  g_f3[64 * S3];
__device__ double2 g_sp1[16 * 1152];
__device__ double2 g_sp2[32 * 576];
__device__ double2 g_sp3[64 * 288];
__device__ float  g_mean[3][64];
__device__ float  g_rstd[3][64];
__device__ float  g_heads[6][NPOS];
__device__ float  g_tr[NPOS * 6];

// ---- packed f32x2 helpers (FFMA2) ----
__device__ __forceinline__ unsigned long long pk2(float lo, float hi) {
    unsigned long long r;
    asm("mov.b64 %0, {%1, %2};" : "=l"(r) : "f"(lo), "f"(hi));
    return r;
}
__device__ __forceinline__ void fma2(unsigned long long& acc, unsigned long long a, unsigned long long b) {
    asm("fma.rn.f32x2 %0, %1, %2, %3;" : "=l"(acc) : "l"(a), "l"(b), "l"(acc));
}
__device__ __forceinline__ float2 unpk(unsigned long long v) {
    float2 f;
    asm("mov.b64 {%0, %1}, %2;" : "=f"(f.x), "=f"(f.y) : "l"(v));
    return f;
}
__device__ __forceinline__ void wred2(double& s, double& q) {
#pragma unroll
    for (int off = 16; off; off >>= 1) {
        s += __shfl_down_sync(0xffffffffu, s, off);
        q += __shfl_down_sync(0xffffffffu, q, off);
    }
}

// ---------------- conv1: 1 -> 16, 3x3, s1, p1; FFMA2; z-split; fused stats ----------------
__global__ void __launch_bounds__(128) k_conv1(const float* __restrict__ img, const float* __restrict__ w) {
    __shared__ float2 sW2[4 * 9];
    __shared__ double sRed[8][4], qRed[8][4];
    int tid = threadIdx.x;
    int z = blockIdx.z;
    if (tid < 36) {
        int pr = tid / 9, k = tid % 9;
        int oc0 = z * 8 + 2 * pr;
        sW2[tid] = make_float2(w[oc0 * 9 + k], w[(oc0 + 1) * 9 + k]);
    }
    __syncthreads();
    int xg = tid & 31, y = tid >> 5;
    int x0 = blockIdx.x * 128 + 4 * xg;
    int yy = blockIdx.y * 4 + y;
    unsigned long long acc[16];
#pragma unroll
    for (int i = 0; i < 16; i++) acc[i] = 0ull;
#pragma unroll
    for (int ky = 0; ky < 3; ky++) {
        int gy = yy + ky - 1;
        float v[6];
        if (gy >= 0 && gy < 768) {
            float4 a = *(const float4*)&img[gy * 768 + x0];
            v[1] = a.x; v[2] = a.y; v[3] = a.z; v[4] = a.w;
            v[0] = (x0 - 1 >= 0) ? img[gy * 768 + x0 - 1] : 0.f;
            v[5] = (x0 + 4 < 768) ? img[gy * 768 + x0 + 4] : 0.f;
        } else {
#pragma unroll
            for (int c = 0; c < 6; c++) v[c] = 0.f;
        }
        unsigned long long pk[6];
#pragma unroll
        for (int j = 0; j < 6; j++) pk[j] = pk2(v[j], v[j]);
#pragma unroll
        for (int p = 0; p < 4; p++) {
            float2 w0 = sW2[p * 9 + ky * 3 + 0];
            float2 w1 = sW2[p * 9 + ky * 3 + 1];
            float2 w2 = sW2[p * 9 + ky * 3 + 2];
            unsigned long long W0 = pk2(w0.x, w0.y), W1 = pk2(w1.x, w1.y), W2 = pk2(w2.x, w2.y);
#pragma unroll
            for (int px = 0; px < 4; px++) {
                fma2(acc[p * 4 + px], pk[px], W0);
                fma2(acc[p * 4 + px], pk[px + 1], W1);
                fma2(acc[p * 4 + px], pk[px + 2], W2);
            }
        }
    }
    double sC[8], qC[8];
#pragma unroll
    for (int p = 0; p < 4; p++) {
        float2 u0 = unpk(acc[p * 4 + 0]), u1 = unpk(acc[p * 4 + 1]);
        float2 u2 = unpk(acc[p * 4 + 2]), u3 = unpk(acc[p * 4 + 3]);
        int oc0 = z * 8 + 2 * p;
        size_t base = (size_t)(1 + yy) * P1 + 4 + x0;
        *(float4*)&g_f1p[oc0 * CH1 + base] = make_float4(u0.x, u1.x, u2.x, u3.x);
        *(float4*)&g_f1p[(oc0 + 1) * CH1 + base] = make_float4(u0.y, u1.y, u2.y, u3.y);
        sC[2 * p]     = (double)u0.x + (double)u1.x + (double)u2.x + (double)u3.x;
        qC[2 * p]     = (double)u0.x * u0.x + (double)u1.x * u1.x + (double)u2.x * u2.x + (double)u3.x * u3.x;
        sC[2 * p + 1] = (double)u0.y + (double)u1.y + (double)u2.y + (double)u3.y;
        qC[2 * p + 1] = (double)u0.y * u0.y + (double)u1.y * u1.y + (double)u2.y * u2.y + (double)u3.y * u3.y;
    }
    int lane = tid & 31, wp = tid >> 5;
#pragma unroll
    for (int c = 0; c < 8; c++) {
        double s = sC[c], q = qC[c];
        wred2(s, q);
        if (lane == 0) { sRed[c][wp] = s; qRed[c][wp] = q; }
    }
    __syncthreads();
    if (tid < 8) {
        double s = sRed[tid][0] + sRed[tid][1] + sRed[tid][2] + sRed[tid][3];
        double q = qRed[tid][0] + qRed[tid][1] + qRed[tid][2] + qRed[tid][3];
        int oc = z * 8 + tid;
        g_sp1[oc * 1152 + blockIdx.y * 6 + blockIdx.x] = make_double2(s, q);
    }
}

// ---------------- fused stat finalize + parallel border fill ----------------
__global__ void k_redfb(int stage) {
    int ch = blockIdx.x, seg = blockIdx.y, nseg = gridDim.y, tid = threadIdx.x;
    const double2* sp; int NB, elems;
    if (stage == 0)      { sp = g_sp1 + ch * 1152; NB = 1152; elems = S1; }
    else if (stage == 1) { sp = g_sp2 + ch * 576;  NB = 576;  elems = S2; }
    else                 { sp = g_sp3 + ch * 288;  NB = 288;  elems = S3; }
    double s = 0.0, q = 0.0;
    for (int i = tid; i < NB; i += 256) { double2 v = sp[i]; s += v.x; q += v.y; }
    __shared__ double ss[256], sq[256];
    __shared__ float smean;
    ss[tid] = s; sq[tid] = q;
    __syncthreads();
    for (int o = 128; o > 0; o >>= 1) {
        if (tid < o) { ss[tid] += ss[tid + o]; sq[tid] += sq[tid + o]; }
        __syncthreads();
    }
    if (tid == 0) {
        double m = ss[0] / (double)elems;
        if (seg == 0) {
            double var = sq[0] / (double)elems - m * m;
            g_mean[stage][ch] = (float)m;
            g_rstd[stage][ch] = (float)(1.0 / sqrt(var + 1e-5));
        }
        smean = (float)m;
    }
    __syncthreads();
    if (stage == 2) return;
    float m = smean;
    float* base; int pitch, rows;
    if (stage == 0) { base = g_f1p + (size_t)ch * CH1; pitch = P1; rows = R1; }
    else            { base = g_f2p + (size_t)ch * CH2; pitch = P2; rows = R2; }
    float4 mv = make_float4(m, m, m, m);
    if (seg == 0)
        for (int i = tid * 4; i < pitch; i += 1024) *(float4*)(base + i) = mv;
    if (seg == nseg - 1)
        for (int i = tid * 4; i < pitch; i += 1024) *(float4*)(base + (size_t)(rows - 1) * pitch + i) = mv;
    for (int r = 1 + seg * 256 + tid; r < rows - 1; r += nseg * 256) {
        *(float4*)(base + (size_t)r * pitch) = mv;
        *(float4*)(base + (size_t)r * pitch + pitch - 4) = mv;
    }
}

// ---------------- conv2: 16 -> 32, 3x3, s2, p1; pipelined fill; FFMA2; fused stats ------
// (R8-winning form: scalar smem tile + register dup-packs)
__global__ void __launch_bounds__(256) k_conv2(const float* __restrict__ w) {
    __shared__ float2 sW2[16 * 16 * 9];
    __shared__ float  sIn[2][17 * 68];
    __shared__ float2 sMR[16];
    __shared__ double sRed[32][2], qRed[32][2];
    int tid = threadIdx.x;
    for (int i = tid; i < 2304; i += 256) {
        int ic = i / 144, r = i % 144, pr = r / 9, k = r % 9;
        int oc0 = 2 * pr;
        sW2[i] = make_float2(w[(oc0 * 16 + ic) * 9 + k], w[((oc0 + 1) * 16 + ic) * 9 + k]);
    }
    if (tid < 16) {
        float m = g_mean[0][tid], rs = g_rstd[0][tid];
        sMR[tid] = make_float2(rs, -m * rs);
    }
    int xg = tid & 7, y = (tid >> 3) & 7, ocg = tid >> 6;
    int ox0 = blockIdx.x * 32, oy0 = blockIdx.y * 8;
    int goff[5], soff[5];
#pragma unroll
    for (int j = 0; j < 5; j++) {
        int e = tid + j * 256;
        int r = e / 65, c = e % 65;
        goff[j] = (2 * oy0 + r) * P1 + 3 + 2 * ox0 + c;
        soff[j] = r * 68 + c;
    }
    float vals[5];
#pragma unroll
    for (int j = 0; j < 5; j++) if (tid + j * 256 < 1105) vals[j] = g_f1p[goff[j]];
    unsigned long long acc[16];
#pragma unroll
    for (int i = 0; i < 16; i++) acc[i] = 0ull;
    int r0 = 2 * y, c0 = 8 * xg;
    __syncthreads();
#pragma unroll 1
    for (int ic = 0; ic < 16; ic++) {
        float2 mr = sMR[ic];
        float* buf = sIn[ic & 1];
#pragma unroll
        for (int j = 0; j < 5; j++)
            if (tid + j * 256 < 1105) buf[soff[j]] = fmaxf(fmaf(vals[j], mr.x, mr.y), 0.f);
        __syncthreads();
        if (ic < 15) {
            const float* srcn = g_f1p + (size_t)(ic + 1) * CH1;
#pragma unroll
            for (int j = 0; j < 5; j++) if (tid + j * 256 < 1105) vals[j] = srcn[goff[j]];
        }
        const float2* wbase = &sW2[(ic * 16 + ocg * 4) * 9];
#pragma unroll
        for (int ky = 0; ky < 3; ky++) {
            const float* row = &buf[(r0 + ky) * 68 + c0];
            float4 a = *(const float4*)row;
            float4 b = *(const float4*)(row + 4);
            float v8 = row[8];
            unsigned long long pk[9];
            pk[0] = pk2(a.x, a.x); pk[1] = pk2(a.y, a.y); pk[2] = pk2(a.z, a.z);
            pk[3] = pk2(a.w, a.w); pk[4] = pk2(b.x, b.x); pk[5] = pk2(b.y, b.y);
            pk[6] = pk2(b.z, b.z); pk[7] = pk2(b.w, b.w); pk[8] = pk2(v8, v8);
#pragma unroll
            for (int p = 0; p < 4; p++) {
                float2 w0 = wbase[p * 9 + ky * 3 + 0];
                float2 w1 = wbase[p * 9 + ky * 3 + 1];
                float2 w2 = wbase[p * 9 + ky * 3 + 2];
                unsigned long long W0 = pk2(w0.x, w0.y), W1 = pk2(w1.x, w1.y), W2 = pk2(w2.x, w2.y);
#pragma unroll
                for (int px = 0; px < 4; px++) {
                    fma2(acc[p * 4 + px], pk[2 * px + 0], W0);
                    fma2(acc[p * 4 + px], pk[2 * px + 1], W1);
                    fma2(acc[p * 4 + px], pk[2 * px + 2], W2);
                }
            }
        }
    }
    int oy = oy0 + y, oxb = ox0 + 4 * xg;
    size_t obase = (size_t)(1 + oy) * P2 + 4 + oxb;
    double sC[8], qC[8];
#pragma unroll
    for (int p = 0; p < 4; p++) {
        float2 u0 = unpk(acc[p * 4 + 0]), u1 = unpk(acc[p * 4 + 1]);
        float2 u2 = unpk(acc[p * 4 + 2]), u3 = unpk(acc[p * 4 + 3]);
        int oc0 = ocg * 8 + 2 * p;
        *(float4*)&g_f2p[oc0 * CH2 + obase] = make_float4(u0.x, u1.x, u2.x, u3.x);
        *(float4*)&g_f2p[(oc0 + 1) * CH2 + obase] = make_float4(u0.y, u1.y, u2.y, u3.y);
        sC[2 * p]     = (double)u0.x + (double)u1.x + (double)u2.x + (double)u3.x;
        qC[2 * p]     = (double)u0.x * u0.x + (double)u1.x * u1.x + (double)u2.x * u2.x + (double)u3.x * u3.x;
        sC[2 * p + 1] = (double)u0.y + (double)u1.y + (double)u2.y + (double)u3.y;
        qC[2 * p + 1] = (double)u0.y * u0.y + (double)u1.y * u1.y + (double)u2.y * u2.y + (double)u3.y * u3.y;
    }
    int lane = tid & 31, wp = tid >> 5;
#pragma unroll
    for (int c = 0; c < 8; c++) {
        double s = sC[c], q = qC[c];
        wred2(s, q);
        if (lane == 0) { sRed[ocg * 8 + c][wp & 1] = s; qRed[ocg * 8 + c][wp & 1] = q; }
    }
    __syncthreads();
    if (tid < 32) {
        double s = sRed[tid][0] + sRed[tid][1];
        double q = qRed[tid][0] + qRed[tid][1];
        g_sp2[tid * 576 + blockIdx.y * 12 + blockIdx.x] = make_double2(s, q);
    }
}

// ---------------- conv3: 32 -> 64, 3x3, s2, p1; pipelined fill; FFMA2; z-split; fused stats --
__global__ void __launch_bounds__(128) k_conv3(const float* __restrict__ w) {
    __shared__ float2 sW2[32 * 16 * 9];
    __shared__ float  sIn[2][17 * 36];
    __shared__ float2 sMR[32];
    int tid = threadIdx.x;
    int z = blockIdx.z;
    for (int i = tid; i < 4608; i += 128) {
        int ic = i / 144, r = i % 144, pr = r / 9, k = r % 9;
        int oc0 = z * 32 + 2 * pr;
        sW2[i] = make_float2(w[(oc0 * 32 + ic) * 9 + k], w[((oc0 + 1) * 32 + ic) * 9 + k]);
    }
    if (tid < 32) {
        float m = g_mean[1][tid], rs = g_rstd[1][tid];
        sMR[tid] = make_float2(rs, -m * rs);
    }
    int xg = tid & 3, y = (tid >> 2) & 7, ocg = (tid >> 5) & 3;
    int ox0 = blockIdx.x * 16, oy0 = blockIdx.y * 8;
    int goff[5], soff[5];
#pragma unroll
    for (int j = 0; j < 5; j++) {
        int e = tid + j * 128;
        int r = e / 33, c = e % 33;
        goff[j] = (2 * oy0 + r) * P2 + 3 + 2 * ox0 + c;
        soff[j] = r * 36 + c;
    }
    float vals[5];
#pragma unroll
    for (int j = 0; j < 5; j++) if (tid + j * 128 < 561) vals[j] = g_f2p[goff[j]];
    unsigned long long acc[16];
#pragma unroll
    for (int i = 0; i < 16; i++) acc[i] = 0ull;
    int r0 = 2 * y, c0 = 8 * xg;
    __syncthreads();
#pragma unroll 1
    for (int ic = 0; ic < 32; ic++) {
        float2 mr = sMR[ic];
        float* buf = sIn[ic & 1];
#pragma unroll
        for (int j = 0; j < 5; j++)
            if (tid + j * 128 < 561) buf[soff[j]] = fmaxf(fmaf(vals[j], mr.x, mr.y), 0.f);
        __syncthreads();
        if (ic < 31) {
            const float* srcn = g_f2p + (size_t)(ic + 1) * CH2;
#pragma unroll
            for (int j = 0; j < 5; j++) if (tid + j * 128 < 561) vals[j] = srcn[goff[j]];
        }
        const float2* wbase = &sW2[(ic * 16 + ocg * 4) * 9];
#pragma unroll
        for (int ky = 0; ky < 3; ky++) {
            const float* row = &buf[(r0 + ky) * 36 + c0];
            float4 a = *(const float4*)row;
            float4 b = *(const float4*)(row + 4);
            float v8 = row[8];
            unsigned long long pk[9];
            pk[0] = pk2(a.x, a.x); pk[1] = pk2(a.y, a.y); pk[2] = pk2(a.z, a.z);
            pk[3] = pk2(a.w, a.w); pk[4] = pk2(b.x, b.x); pk[5] = pk2(b.y, b.y);
            pk[6] = pk2(b.z, b.z); pk[7] = pk2(b.w, b.w); pk[8] = pk2(v8, v8);
#pragma unroll
            for (int p = 0; p < 4; p++) {
                float2 w0 = wbase[p * 9 + ky * 3 + 0];
                float2 w1 = wbase[p * 9 + ky * 3 + 1];
                float2 w2 = wbase[p * 9 + ky * 3 + 2];
                unsigned long long W0 = pk2(w0.x, w0.y), W1 = pk2(w1.x, w1.y), W2 = pk2(w2.x, w2.y);
#pragma unroll
                for (int px = 0; px < 4; px++) {
                    fma2(acc[p * 4 + px], pk[2 * px + 0], W0);
                    fma2(acc[p * 4 + px], pk[2 * px + 1], W1);
                    fma2(acc[p * 4 + px], pk[2 * px + 2], W2);
                }
            }
        }
    }
    int oy = oy0 + y, oxb = ox0 + 4 * xg;
    double sC[8], qC[8];
#pragma unroll
    for (int p = 0; p < 4; p++) {
        float2 u0 = unpk(acc[p * 4 + 0]), u1 = unpk(acc[p * 4 + 1]);
        float2 u2 = unpk(acc[p * 4 + 2]), u3 = unpk(acc[p * 4 + 3]);
        int oc0 = z * 32 + ocg * 8 + 2 * p;
        *(float4*)&g_f3[oc0 * S3 + oy * 192 + oxb] = make_float4(u0.x, u1.x, u2.x, u3.x);
        *(float4*)&g_f3[(oc0 + 1) * S3 + oy * 192 + oxb] = make_float4(u0.y, u1.y, u2.y, u3.y);
        sC[2 * p]     = (double)u0.x + (double)u1.x + (double)u2.x + (double)u3.x;
        qC[2 * p]     = (double)u0.x * u0.x + (double)u1.x * u1.x + (double)u2.x * u2.x + (double)u3.x * u3.x;
        sC[2 * p + 1] = (double)u0.y + (double)u1.y + (double)u2.y + (double)u3.y;
        qC[2 * p + 1] = (double)u0.y * u0.y + (double)u1.y * u1.y + (double)u2.y * u2.y + (double)u3.y * u3.y;
    }
    int lane = tid & 31;
#pragma unroll
    for (int c = 0; c < 8; c++) {
        double s = sC[c], q = qC[c];
        wred2(s, q);
        if (lane == 0)
            g_sp3[(z * 32 + ocg * 8 + c) * 288 + blockIdx.y * 12 + blockIdx.x] = make_double2(s, q);
    }
}

// ---------------- heads ----------------
__global__ void k_heads(const float* __restrict__ pw, const float* __restrict__ pb,
                        const float* __restrict__ tw, const float* __restrict__ tb,
                        const float* __restrict__ shw, const float* __restrict__ shb,
                        const float* __restrict__ scw, const float* __restrict__ scb,
                        const float* __restrict__ tiw, const float* __restrict__ tib) {
    __shared__ float sw[1536];
    __shared__ float sb[6];
    int tid = threadIdx.x;
    for (int i = tid; i < 1536; i += 128) {
        int h = i / 256, r = i % 256;
        const float* s; int off = r;
        if (h == 0) s = pw;
        else if (h == 1) s = tw;
        else if (h == 2) s = shw;
        else if (h == 3) { s = shw; off = r + 256; }
        else if (h == 4) s = scw;
        else s = tiw;
        sw[i] = s[off];
    }
    if (tid == 0) { sb[0] = pb[0]; sb[1] = tb[0]; sb[2] = shb[0]; sb[3] = shb[1]; sb[4] = scb[0]; sb[5] = tib[0]; }
    __syncthreads();
    int n = blockIdx.x * 128 + tid;
    int y = n / 96, x = n % 96;
    float acc[6] = {0.f, 0.f, 0.f, 0.f, 0.f, 0.f};
#pragma unroll 4
    for (int ic = 0; ic < 64; ic++) {
        float m = g_mean[2][ic], rs = g_rstd[2][ic];
        int base = ic * S3 + (2 * y) * 192 + 2 * x;
        float v0 = (g_f3[base] - m) * rs;       v0 = v0 > 0.f ? v0 : 0.f;
        float v1 = (g_f3[base + 1] - m) * rs;   v1 = v1 > 0.f ? v1 : 0.f;
        float v2 = (g_f3[base + 192] - m) * rs; v2 = v2 > 0.f ? v2 : 0.f;
        float v3 = (g_f3[base + 193] - m) * rs; v3 = v3 > 0.f ? v3 : 0.f;
#pragma unroll
        for (int h = 0; h < 6; h++) {
            const float* ww = &sw[h * 256 + ic * 4];
            acc[h] += v0 * ww[0] + v1 * ww[1] + v2 * ww[2] + v3 * ww[3];
        }
    }
    g_heads[0][n] = 3.14159f * tanhf(acc[0] + sb[0]);
    g_heads[1][n] = 3.14159f * tanhf(acc[1] + sb[1]);
    g_heads[2][n] = 0.2f * tanhf(acc[2] + sb[2]);
    g_heads[3][n] = 0.2f * tanhf(acc[3] + sb[3]);
    float sc = 1.f + 0.25f * tanhf(acc[4] + sb[4]);
    g_heads[4][n] = fminf(fmaxf(sc, 0.8f), 1.25f);
    float ti = 1.f + 0.8f * tanhf(acc[5] + sb[5]);
    g_heads[5][n] = fminf(fmaxf(ti, 1.0f), 1.8f);
}

// ---------------- transform build + aff output ----------------
__global__ void k_transform(float* __restrict__ aff) {
    int n = blockIdx.x * 256 + threadIdx.x;
    if (n >= NPOS) return;
    float psi = g_heads[0][n], th = g_heads[1][n];
    const float* sf = &g_heads[2][0];
    float sx = sf[2 * n], sy = sf[2 * n + 1];
    float s = g_heads[4][n], t = g_heads[5][n];
    float cp = cosf(psi), sp = sinf(psi), ct = cosf(th), st = sinf(th);
    float a = t * ct, b = -t * st, c = st / t, d = ct / t;
    float A00 = s * (cp * a - sp * c), A01 = s * (cp * b - sp * d);
    float A10 = s * (sp * a + cp * c), A11 = s * (sp * b + cp * d);
    float* tr = &g_tr[n * 6];
    tr[0] = A00; tr[1] = A01; tr[2] = sx; tr[3] = A10; tr[4] = A11; tr[5] = sy;
    float* af = aff + (size_t)n * 6;
    af[0] = 32.f * A00; af[1] = 32.f * A01; af[2] = (float)(4 + 8 * (n % 96)) + 32.f * sx;
    af[3] = 32.f * A10; af[4] = 32.f * A11; af[5] = (float)(4 + 8 * (n / 96)) + 32.f * sy;
}

// ---------------- bilinear sampler: 4 consecutive samples/thread, float4 store ----------
__device__ __forceinline__ float samp(const float* __restrict__ img, int py, int px, int yy, int xx) {
    if ((unsigned)xx >= 144u || (unsigned)yy >= 144u) return 0.f;
    int r = py * 8 + yy - 68, c = px * 8 + xx - 68;
    if ((unsigned)r >= 768u || (unsigned)c >= 768u) return 0.f;
    return img[r * 768 + c];
}

__global__ void k_sample(const float* __restrict__ img, float* __restrict__ outp) {
    int n = blockIdx.x;
    __shared__ float tr[6];
    if (threadIdx.x < 6) tr[threadIdx.x] = g_tr[n * 6 + threadIdx.x];
    __syncthreads();
    int px = n % 96, py = n / 96;
    int t4 = threadIdx.x * 4;
    int h = t4 >> 5, w0 = t4 & 31;
    float Y = (h + 0.5f) * 0.0625f - 1.f;
    float o[4];
#pragma unroll
    for (int j = 0; j < 4; j++) {
        float X = (w0 + j + 0.5f) * 0.0625f - 1.f;
        float gx = (tr[0] * X + tr[1] * Y + tr[2]) * (1.f / 4.5f);
        float gy = (tr[3] * X + tr[4] * Y + tr[5]) * (1.f / 4.5f);
        float ix = gx * 72.f + 71.5f;
        float iy = gy * 72.f + 71.5f;
        float x0 = floorf(ix), y0 = floorf(iy);
        float wx = ix - x0, wy = iy - y0;
        int xi = (int)x0, yi = (int)y0;
        float v00 = samp(img, py, px, yi, xi);
        float v01 = samp(img, py, px, yi, xi + 1);
        float v10 = samp(img, py, px, yi + 1, xi);
        float v11 = samp(img, py, px, yi + 1, xi + 1);
        o[j] = (1.f - wy) * ((1.f - wx) * v00 + wx * v01) + wy * ((1.f - wx) * v10 + wx * v11);
    }
    *(float4*)&outp[(size_t)n * 1024 + t4] = make_float4(o[0], o[1], o[2], o[3]);
}

extern "C" void kernel_launch(void* const* d_in, const int* in_sizes, int n_in,
                              void* d_out, int out_size) {
    const float* img = (const float*)d_in[0];
    const float* w1 = (const float*)d_in[1];
    const float* w2 = (const float*)d_in[2];
    const float* w3 = (const float*)d_in[3];
    const float* pw = (const float*)d_in[4];  const float* pb = (const float*)d_in[5];
    const float* tw = (const float*)d_in[6];  const float* tb = (const float*)d_in[7];
    const float* shw = (const float*)d_in[8]; const float* shb = (const float*)d_in[9];
    const float* scw = (const float*)d_in[10]; const float* scb = (const float*)d_in[11];
    const float* tiw = (const float*)d_in[12]; const float* tib = (const float*)d_in[13];

    float* out = (float*)d_out;          // transformed: 9216*1*32*32 floats
    float* aff = out + 9216 * 1024;      // aff: 9216*2*3 floats

    k_conv1<<<dim3(6, 192, 2), 128>>>(img, w1);
    k_redfb<<<dim3(16, 8), 256>>>(0);
    k_conv2<<<dim3(12, 48), 256>>>(w2);
    k_redfb<<<dim3(32, 8), 256>>>(1);
    k_conv3<<<dim3(12, 24, 2), 128>>>(w3);
    k_redfb<<<dim3(64, 1), 256>>>(2);
    k_heads<<<72, 128>>>(pw, pb, tw, tb, shw, shb, scw, scb, tiw, tib);
    k_transform<<<36, 256>>>(aff);
    k_sample<<<NPOS, 256>>>(img, out);
}

// round 11
// speedup vs baseline: 1.4389x; 1.0102x over previous
#include <cuda_runtime.h>
#include <math.h>

#define S1 589824   // 768*768
#define S2 147456   // 384*384
#define S3 36864    // 192*192
#define NPOS 9216   // 96*96

// padded pitched buffers: interior origin (row 1, col 4)
#define P1 776
#define R1 770
#define CH1 (770*776)
#define P2 392
#define R2 386
#define CH2 (386*392)

__device__ float  g_f1p[16 * CH1];
__device__ float  g_f2p[32 * CH2];
__device__ float  g_f3[64 * S3];
__device__ double2 g_sp1[16 * 1152];
__device__ double2 g_sp2[32 * 576];
__device__ double2 g_sp3[64 * 288];
__device__ float  g_mean[3][64];
__device__ float  g_rstd[3][64];
__device__ float  g_heads[6][NPOS];

// ---- packed f32x2 helpers (FFMA2) ----
__device__ __forceinline__ unsigned long long pk2(float lo, float hi) {
    unsigned long long r;
    asm("mov.b64 %0, {%1, %2};" : "=l"(r) : "f"(lo), "f"(hi));
    return r;
}
__device__ __forceinline__ void fma2(unsigned long long& acc, unsigned long long a, unsigned long long b) {
    asm("fma.rn.f32x2 %0, %1, %2, %3;" : "=l"(acc) : "l"(a), "l"(b), "l"(acc));
}
__device__ __forceinline__ float2 unpk(unsigned long long v) {
    float2 f;
    asm("mov.b64 {%0, %1}, %2;" : "=f"(f.x), "=f"(f.y) : "l"(v));
    return f;
}
__device__ __forceinline__ void wred2(double& s, double& q) {
#pragma unroll
    for (int off = 16; off; off >>= 1) {
        s += __shfl_down_sync(0xffffffffu, s, off);
        q += __shfl_down_sync(0xffffffffu, q, off);
    }
}

// ---------------- conv1: 1 -> 16, 3x3, s1, p1; FFMA2; z-split; fused stats ----------------
__global__ void __launch_bounds__(128) k_conv1(const float* __restrict__ img, const float* __restrict__ w) {
    __shared__ float2 sW2[4 * 9];
    __shared__ double sRed[8][4], qRed[8][4];
    int tid = threadIdx.x;
    int z = blockIdx.z;
    if (tid < 36) {
        int pr = tid / 9, k = tid % 9;
        int oc0 = z * 8 + 2 * pr;
        sW2[tid] = make_float2(w[oc0 * 9 + k], w[(oc0 + 1) * 9 + k]);
    }
    __syncthreads();
    int xg = tid & 31, y = tid >> 5;
    int x0 = blockIdx.x * 128 + 4 * xg;
    int yy = blockIdx.y * 4 + y;
    const unsigned long long* wb = (const unsigned long long*)sW2;
    unsigned long long acc[16];
#pragma unroll
    for (int i = 0; i < 16; i++) acc[i] = 0ull;
#pragma unroll
    for (int ky = 0; ky < 3; ky++) {
        int gy = yy + ky - 1;
        float v[6];
        if (gy >= 0 && gy < 768) {
            float4 a = *(const float4*)&img[gy * 768 + x0];
            v[1] = a.x; v[2] = a.y; v[3] = a.z; v[4] = a.w;
            v[0] = (x0 - 1 >= 0) ? img[gy * 768 + x0 - 1] : 0.f;
            v[5] = (x0 + 4 < 768) ? img[gy * 768 + x0 + 4] : 0.f;
        } else {
#pragma unroll
            for (int c = 0; c < 6; c++) v[c] = 0.f;
        }
        unsigned long long pk[6];
#pragma unroll
        for (int j = 0; j < 6; j++) pk[j] = pk2(v[j], v[j]);
#pragma unroll
        for (int p = 0; p < 4; p++) {
            unsigned long long W0 = wb[p * 9 + ky * 3 + 0];
            unsigned long long W1 = wb[p * 9 + ky * 3 + 1];
            unsigned long long W2 = wb[p * 9 + ky * 3 + 2];
#pragma unroll
            for (int px = 0; px < 4; px++) {
                fma2(acc[p * 4 + px], pk[px], W0);
                fma2(acc[p * 4 + px], pk[px + 1], W1);
                fma2(acc[p * 4 + px], pk[px + 2], W2);
            }
        }
    }
    double sC[8], qC[8];
#pragma unroll
    for (int p = 0; p < 4; p++) {
        float2 u0 = unpk(acc[p * 4 + 0]), u1 = unpk(acc[p * 4 + 1]);
        float2 u2 = unpk(acc[p * 4 + 2]), u3 = unpk(acc[p * 4 + 3]);
        int oc0 = z * 8 + 2 * p;
        size_t base = (size_t)(1 + yy) * P1 + 4 + x0;
        *(float4*)&g_f1p[oc0 * CH1 + base] = make_float4(u0.x, u1.x, u2.x, u3.x);
        *(float4*)&g_f1p[(oc0 + 1) * CH1 + base] = make_float4(u0.y, u1.y, u2.y, u3.y);
        sC[2 * p]     = (double)u0.x + (double)u1.x + (double)u2.x + (double)u3.x;
        qC[2 * p]     = (double)u0.x * u0.x + (double)u1.x * u1.x + (double)u2.x * u2.x + (double)u3.x * u3.x;
        sC[2 * p + 1] = (double)u0.y + (double)u1.y + (double)u2.y + (double)u3.y;
        qC[2 * p + 1] = (double)u0.y * u0.y + (double)u1.y * u1.y + (double)u2.y * u2.y + (double)u3.y * u3.y;
    }
    int lane = tid & 31, wp = tid >> 5;
#pragma unroll
    for (int c = 0; c < 8; c++) {
        double s = sC[c], q = qC[c];
        wred2(s, q);
        if (lane == 0) { sRed[c][wp] = s; qRed[c][wp] = q; }
    }
    __syncthreads();
    if (tid < 8) {
        double s = sRed[tid][0] + sRed[tid][1] + sRed[tid][2] + sRed[tid][3];
        double q = qRed[tid][0] + qRed[tid][1] + qRed[tid][2] + qRed[tid][3];
        int oc = z * 8 + tid;
        g_sp1[oc * 1152 + blockIdx.y * 6 + blockIdx.x] = make_double2(s, q);
    }
}

// ---------------- fused stat finalize + parallel border fill ----------------
__global__ void k_redfb(int stage) {
    int ch = blockIdx.x, seg = blockIdx.y, nseg = gridDim.y, tid = threadIdx.x;
    const double2* sp; int NB, elems;
    if (stage == 0)      { sp = g_sp1 + ch * 1152; NB = 1152; elems = S1; }
    else if (stage == 1) { sp = g_sp2 + ch * 576;  NB = 576;  elems = S2; }
    else                 { sp = g_sp3 + ch * 288;  NB = 288;  elems = S3; }
    double s = 0.0, q = 0.0;
    for (int i = tid; i < NB; i += 256) { double2 v = sp[i]; s += v.x; q += v.y; }
    __shared__ double ss[256], sq[256];
    __shared__ float smean;
    ss[tid] = s; sq[tid] = q;
    __syncthreads();
    for (int o = 128; o > 0; o >>= 1) {
        if (tid < o) { ss[tid] += ss[tid + o]; sq[tid] += sq[tid + o]; }
        __syncthreads();
    }
    if (tid == 0) {
        double m = ss[0] / (double)elems;
        if (seg == 0) {
            double var = sq[0] / (double)elems - m * m;
            g_mean[stage][ch] = (float)m;
            g_rstd[stage][ch] = (float)(1.0 / sqrt(var + 1e-5));
        }
        smean = (float)m;
    }
    __syncthreads();
    if (stage == 2) return;
    float m = smean;
    float* base; int pitch, rows;
    if (stage == 0) { base = g_f1p + (size_t)ch * CH1; pitch = P1; rows = R1; }
    else            { base = g_f2p + (size_t)ch * CH2; pitch = P2; rows = R2; }
    float4 mv = make_float4(m, m, m, m);
    if (seg == 0)
        for (int i = tid * 4; i < pitch; i += 1024) *(float4*)(base + i) = mv;
    if (seg == nseg - 1)
        for (int i = tid * 4; i < pitch; i += 1024) *(float4*)(base + (size_t)(rows - 1) * pitch + i) = mv;
    for (int r = 1 + seg * 256 + tid; r < rows - 1; r += nseg * 256) {
        *(float4*)(base + (size_t)r * pitch) = mv;
        *(float4*)(base + (size_t)r * pitch + pitch - 4) = mv;
    }
}

// ---------------- conv2: 16 -> 32, 3x3, s2, p1; pipelined fill; FFMA2; fused stats ------
__global__ void __launch_bounds__(256) k_conv2(const float* __restrict__ w) {
    __shared__ float2 sW2[16 * 16 * 9];
    __shared__ float  sIn[2][17 * 68];
    __shared__ float2 sMR[16];
    __shared__ double sRed[32][2], qRed[32][2];
    int tid = threadIdx.x;
    for (int i = tid; i < 2304; i += 256) {
        int ic = i / 144, r = i % 144, pr = r / 9, k = r % 9;
        int oc0 = 2 * pr;
        sW2[i] = make_float2(w[(oc0 * 16 + ic) * 9 + k], w[((oc0 + 1) * 16 + ic) * 9 + k]);
    }
    if (tid < 16) {
        float m = g_mean[0][tid], rs = g_rstd[0][tid];
        sMR[tid] = make_float2(rs, -m * rs);
    }
    int xg = tid & 7, y = (tid >> 3) & 7, ocg = tid >> 6;
    int ox0 = blockIdx.x * 32, oy0 = blockIdx.y * 8;
    int goff[5], soff[5];
#pragma unroll
    for (int j = 0; j < 5; j++) {
        int e = tid + j * 256;
        int r = e / 65, c = e % 65;
        goff[j] = (2 * oy0 + r) * P1 + 3 + 2 * ox0 + c;
        soff[j] = r * 68 + c;
    }
    float vals[5];
#pragma unroll
    for (int j = 0; j < 5; j++) if (tid + j * 256 < 1105) vals[j] = g_f1p[goff[j]];
    unsigned long long acc[16];
#pragma unroll
    for (int i = 0; i < 16; i++) acc[i] = 0ull;
    int r0 = 2 * y, c0 = 8 * xg;
    __syncthreads();
#pragma unroll 1
    for (int ic = 0; ic < 16; ic++) {
        float2 mr = sMR[ic];
        float* buf = sIn[ic & 1];
#pragma unroll
        for (int j = 0; j < 5; j++)
            if (tid + j * 256 < 1105) buf[soff[j]] = fmaxf(fmaf(vals[j], mr.x, mr.y), 0.f);
        __syncthreads();
        if (ic < 15) {
            const float* srcn = g_f1p + (size_t)(ic + 1) * CH1;
#pragma unroll
            for (int j = 0; j < 5; j++) if (tid + j * 256 < 1105) vals[j] = srcn[goff[j]];
        }
        const unsigned long long* wb = (const unsigned long long*)&sW2[(ic * 16 + ocg * 4) * 9];
#pragma unroll
        for (int ky = 0; ky < 3; ky++) {
            const float* row = &buf[(r0 + ky) * 68 + c0];
            float4 a = *(const float4*)row;
            float4 b = *(const float4*)(row + 4);
            float v8 = row[8];
            unsigned long long pk[9];
            pk[0] = pk2(a.x, a.x); pk[1] = pk2(a.y, a.y); pk[2] = pk2(a.z, a.z);
            pk[3] = pk2(a.w, a.w); pk[4] = pk2(b.x, b.x); pk[5] = pk2(b.y, b.y);
            pk[6] = pk2(b.z, b.z); pk[7] = pk2(b.w, b.w); pk[8] = pk2(v8, v8);
#pragma unroll
            for (int p = 0; p < 4; p++) {
                unsigned long long W0 = wb[p * 9 + ky * 3 + 0];
                unsigned long long W1 = wb[p * 9 + ky * 3 + 1];
                unsigned long long W2 = wb[p * 9 + ky * 3 + 2];
#pragma unroll
                for (int px = 0; px < 4; px++) {
                    fma2(acc[p * 4 + px], pk[2 * px + 0], W0);
                    fma2(acc[p * 4 + px], pk[2 * px + 1], W1);
                    fma2(acc[p * 4 + px], pk[2 * px + 2], W2);
                }
            }
        }
    }
    int oy = oy0 + y, oxb = ox0 + 4 * xg;
    size_t obase = (size_t)(1 + oy) * P2 + 4 + oxb;
    double sC[8], qC[8];
#pragma unroll
    for (int p = 0; p < 4; p++) {
        float2 u0 = unpk(acc[p * 4 + 0]), u1 = unpk(acc[p * 4 + 1]);
        float2 u2 = unpk(acc[p * 4 + 2]), u3 = unpk(acc[p * 4 + 3]);
        int oc0 = ocg * 8 + 2 * p;
        *(float4*)&g_f2p[oc0 * CH2 + obase] = make_float4(u0.x, u1.x, u2.x, u3.x);
        *(float4*)&g_f2p[(oc0 + 1) * CH2 + obase] = make_float4(u0.y, u1.y, u2.y, u3.y);
        sC[2 * p]     = (double)u0.x + (double)u1.x + (double)u2.x + (double)u3.x;
        qC[2 * p]     = (double)u0.x * u0.x + (double)u1.x * u1.x + (double)u2.x * u2.x + (double)u3.x * u3.x;
        sC[2 * p + 1] = (double)u0.y + (double)u1.y + (double)u2.y + (double)u3.y;
        qC[2 * p + 1] = (double)u0.y * u0.y + (double)u1.y * u1.y + (double)u2.y * u2.y + (double)u3.y * u3.y;
    }
    int lane = tid & 31, wp = tid >> 5;
#pragma unroll
    for (int c = 0; c < 8; c++) {
        double s = sC[c], q = qC[c];
        wred2(s, q);
        if (lane == 0) { sRed[ocg * 8 + c][wp & 1] = s; qRed[ocg * 8 + c][wp & 1] = q; }
    }
    __syncthreads();
    if (tid < 32) {
        double s = sRed[tid][0] + sRed[tid][1];
        double q = qRed[tid][0] + qRed[tid][1];
        g_sp2[tid * 576 + blockIdx.y * 12 + blockIdx.x] = make_double2(s, q);
    }
}

// ---------------- conv3: 32 -> 64, 3x3, s2, p1; pipelined fill; FFMA2; z-split; fused stats --
__global__ void __launch_bounds__(128) k_conv3(const float* __restrict__ w) {
    __shared__ float2 sW2[32 * 16 * 9];
    __shared__ float  sIn[2][17 * 36];
    __shared__ float2 sMR[32];
    int tid = threadIdx.x;
    int z = blockIdx.z;
    for (int i = tid; i < 4608; i += 128) {
        int ic = i / 144, r = i % 144, pr = r / 9, k = r % 9;
        int oc0 = z * 32 + 2 * pr;
        sW2[i] = make_float2(w[(oc0 * 32 + ic) * 9 + k], w[((oc0 + 1) * 32 + ic) * 9 + k]);
    }
    if (tid < 32) {
        float m = g_mean[1][tid], rs = g_rstd[1][tid];
        sMR[tid] = make_float2(rs, -m * rs);
    }
    int xg = tid & 3, y = (tid >> 2) & 7, ocg = (tid >> 5) & 3;
    int ox0 = blockIdx.x * 16, oy0 = blockIdx.y * 8;
    int goff[5], soff[5];
#pragma unroll
    for (int j = 0; j < 5; j++) {
        int e = tid + j * 128;
        int r = e / 33, c = e % 33;
        goff[j] = (2 * oy0 + r) * P2 + 3 + 2 * ox0 + c;
        soff[j] = r * 36 + c;
    }
    float vals[5];
#pragma unroll
    for (int j = 0; j < 5; j++) if (tid + j * 128 < 561) vals[j] = g_f2p[goff[j]];
    unsigned long long acc[16];
#pragma unroll
    for (int i = 0; i < 16; i++) acc[i] = 0ull;
    int r0 = 2 * y, c0 = 8 * xg;
    __syncthreads();
#pragma unroll 1
    for (int ic = 0; ic < 32; ic++) {
        float2 mr = sMR[ic];
        float* buf = sIn[ic & 1];
#pragma unroll
        for (int j = 0; j < 5; j++)
            if (tid + j * 128 < 561) buf[soff[j]] = fmaxf(fmaf(vals[j], mr.x, mr.y), 0.f);
        __syncthreads();
        if (ic < 31) {
            const float* srcn = g_f2p + (size_t)(ic + 1) * CH2;
#pragma unroll
            for (int j = 0; j < 5; j++) if (tid + j * 128 < 561) vals[j] = srcn[goff[j]];
        }
        const unsigned long long* wb = (const unsigned long long*)&sW2[(ic * 16 + ocg * 4) * 9];
#pragma unroll
        for (int ky = 0; ky < 3; ky++) {
            const float* row = &buf[(r0 + ky) * 36 + c0];
            float4 a = *(const float4*)row;
            float4 b = *(const float4*)(row + 4);
            float v8 = row[8];
            unsigned long long pk[9];
            pk[0] = pk2(a.x, a.x); pk[1] = pk2(a.y, a.y); pk[2] = pk2(a.z, a.z);
            pk[3] = pk2(a.w, a.w); pk[4] = pk2(b.x, b.x); pk[5] = pk2(b.y, b.y);
            pk[6] = pk2(b.z, b.z); pk[7] = pk2(b.w, b.w); pk[8] = pk2(v8, v8);
#pragma unroll
            for (int p = 0; p < 4; p++) {
                unsigned long long W0 = wb[p * 9 + ky * 3 + 0];
                unsigned long long W1 = wb[p * 9 + ky * 3 + 1];
                unsigned long long W2 = wb[p * 9 + ky * 3 + 2];
#pragma unroll
                for (int px = 0; px < 4; px++) {
                    fma2(acc[p * 4 + px], pk[2 * px + 0], W0);
                    fma2(acc[p * 4 + px], pk[2 * px + 1], W1);
                    fma2(acc[p * 4 + px], pk[2 * px + 2], W2);
                }
            }
        }
    }
    int oy = oy0 + y, oxb = ox0 + 4 * xg;
    double sC[8], qC[8];
#pragma unroll
    for (int p = 0; p < 4; p++) {
        float2 u0 = unpk(acc[p * 4 + 0]), u1 = unpk(acc[p * 4 + 1]);
        float2 u2 = unpk(acc[p * 4 + 2]), u3 = unpk(acc[p * 4 + 3]);
        int oc0 = z * 32 + ocg * 8 + 2 * p;
        *(float4*)&g_f3[oc0 * S3 + oy * 192 + oxb] = make_float4(u0.x, u1.x, u2.x, u3.x);
        *(float4*)&g_f3[(oc0 + 1) * S3 + oy * 192 + oxb] = make_float4(u0.y, u1.y, u2.y, u3.y);
        sC[2 * p]     = (double)u0.x + (double)u1.x + (double)u2.x + (double)u3.x;
        qC[2 * p]     = (double)u0.x * u0.x + (double)u1.x * u1.x + (double)u2.x * u2.x + (double)u3.x * u3.x;
        sC[2 * p + 1] = (double)u0.y + (double)u1.y + (double)u2.y + (double)u3.y;
        qC[2 * p + 1] = (double)u0.y * u0.y + (double)u1.y * u1.y + (double)u2.y * u2.y + (double)u3.y * u3.y;
    }
    int lane = tid & 31;
#pragma unroll
    for (int c = 0; c < 8; c++) {
        double s = sC[c], q = qC[c];
        wred2(s, q);
        if (lane == 0)
            g_sp3[(z * 32 + ocg * 8 + c) * 288 + blockIdx.y * 12 + blockIdx.x] = make_double2(s, q);
    }
}

// ---------------- heads ----------------
__global__ void k_heads(const float* __restrict__ pw, const float* __restrict__ pb,
                        const float* __restrict__ tw, const float* __restrict__ tb,
                        const float* __restrict__ shw, const float* __restrict__ shb,
                        const float* __restrict__ scw, const float* __restrict__ scb,
                        const float* __restrict__ tiw, const float* __restrict__ tib) {
    __shared__ float sw[1536];
    __shared__ float sb[6];
    int tid = threadIdx.x;
    for (int i = tid; i < 1536; i += 128) {
        int h = i / 256, r = i % 256;
        const float* s; int off = r;
        if (h == 0) s = pw;
        else if (h == 1) s = tw;
        else if (h == 2) s = shw;
        else if (h == 3) { s = shw; off = r + 256; }
        else if (h == 4) s = scw;
        else s = tiw;
        sw[i] = s[off];
    }
    if (tid == 0) { sb[0] = pb[0]; sb[1] = tb[0]; sb[2] = shb[0]; sb[3] = shb[1]; sb[4] = scb[0]; sb[5] = tib[0]; }
    __syncthreads();
    int n = blockIdx.x * 128 + tid;
    int y = n / 96, x = n % 96;
    float acc[6] = {0.f, 0.f, 0.f, 0.f, 0.f, 0.f};
#pragma unroll 4
    for (int ic = 0; ic < 64; ic++) {
        float m = g_mean[2][ic], rs = g_rstd[2][ic];
        int base = ic * S3 + (2 * y) * 192 + 2 * x;
        float v0 = (g_f3[base] - m) * rs;       v0 = v0 > 0.f ? v0 : 0.f;
        float v1 = (g_f3[base + 1] - m) * rs;   v1 = v1 > 0.f ? v1 : 0.f;
        float v2 = (g_f3[base + 192] - m) * rs; v2 = v2 > 0.f ? v2 : 0.f;
        float v3 = (g_f3[base + 193] - m) * rs; v3 = v3 > 0.f ? v3 : 0.f;
#pragma unroll
        for (int h = 0; h < 6; h++) {
            const float* ww = &sw[h * 256 + ic * 4];
            acc[h] += v0 * ww[0] + v1 * ww[1] + v2 * ww[2] + v3 * ww[3];
        }
    }
    g_heads[0][n] = 3.14159f * tanhf(acc[0] + sb[0]);
    g_heads[1][n] = 3.14159f * tanhf(acc[1] + sb[1]);
    g_heads[2][n] = 0.2f * tanhf(acc[2] + sb[2]);
    g_heads[3][n] = 0.2f * tanhf(acc[3] + sb[3]);
    float sc = 1.f + 0.25f * tanhf(acc[4] + sb[4]);
    g_heads[4][n] = fminf(fmaxf(sc, 0.8f), 1.25f);
    float ti = 1.f + 0.8f * tanhf(acc[5] + sb[5]);
    g_heads[5][n] = fminf(fmaxf(ti, 1.0f), 1.8f);
}

// ---------------- bilinear sampler + inline transform/aff (k_transform folded in) --------
__device__ __forceinline__ float samp(const float* __restrict__ img, int py, int px, int yy, int xx) {
    if ((unsigned)xx >= 144u || (unsigned)yy >= 144u) return 0.f;
    int r = py * 8 + yy - 68, c = px * 8 + xx - 68;
    if ((unsigned)r >= 768u || (unsigned)c >= 768u) return 0.f;
    return img[r * 768 + c];
}

__global__ void k_sample(const float* __restrict__ img, float* __restrict__ outp,
                         float* __restrict__ aff) {
    int n = blockIdx.x;
    __shared__ float tr[6];
    if (threadIdx.x == 0) {
        float psi = g_heads[0][n], th = g_heads[1][n];
        const float* sf = &g_heads[2][0];
        float sx = sf[2 * n], sy = sf[2 * n + 1];
        float s = g_heads[4][n], t = g_heads[5][n];
        float cp = cosf(psi), sp = sinf(psi), ct = cosf(th), st = sinf(th);
        float a = t * ct, b = -t * st, c = st / t, d = ct / t;
        float A00 = s * (cp * a - sp * c), A01 = s * (cp * b - sp * d);
        float A10 = s * (sp * a + cp * c), A11 = s * (sp * b + cp * d);
        tr[0] = A00; tr[1] = A01; tr[2] = sx; tr[3] = A10; tr[4] = A11; tr[5] = sy;
        float* af = aff + (size_t)n * 6;
        af[0] = 32.f * A00; af[1] = 32.f * A01; af[2] = (float)(4 + 8 * (n % 96)) + 32.f * sx;
        af[3] = 32.f * A10; af[4] = 32.f * A11; af[5] = (float)(4 + 8 * (n / 96)) + 32.f * sy;
    }
    __syncthreads();
    int px = n % 96, py = n / 96;
    int t4 = threadIdx.x * 4;
    int h = t4 >> 5, w0 = t4 & 31;
    float Y = (h + 0.5f) * 0.0625f - 1.f;
    float o[4];
#pragma unroll
    for (int j = 0; j < 4; j++) {
        float X = (w0 + j + 0.5f) * 0.0625f - 1.f;
        float gx = (tr[0] * X + tr[1] * Y + tr[2]) * (1.f / 4.5f);
        float gy = (tr[3] * X + tr[4] * Y + tr[5]) * (1.f / 4.5f);
        float ix = gx * 72.f + 71.5f;
        float iy = gy * 72.f + 71.5f;
        float x0 = floorf(ix), y0 = floorf(iy);
        float wx = ix - x0, wy = iy - y0;
        int xi = (int)x0, yi = (int)y0;
        float v00 = samp(img, py, px, yi, xi);
        float v01 = samp(img, py, px, yi, xi + 1);
        float v10 = samp(img, py, px, yi + 1, xi);
        float v11 = samp(img, py, px, yi + 1, xi + 1);
        o[j] = (1.f - wy) * ((1.f - wx) * v00 + wx * v01) + wy * ((1.f - wx) * v10 + wx * v11);
    }
    *(float4*)&outp[(size_t)n * 1024 + t4] = make_float4(o[0], o[1], o[2], o[3]);
}

extern "C" void kernel_launch(void* const* d_in, const int* in_sizes, int n_in,
                              void* d_out, int out_size) {
    const float* img = (const float*)d_in[0];
    const float* w1 = (const float*)d_in[1];
    const float* w2 = (const float*)d_in[2];
    const float* w3 = (const float*)d_in[3];
    const float* pw = (const float*)d_in[4];  const float* pb = (const float*)d_in[5];
    const float* tw = (const float*)d_in[6];  const float* tb = (const float*)d_in[7];
    const float* shw = (const float*)d_in[8]; const float* shb = (const float*)d_in[9];
    const float* scw = (const float*)d_in[10]; const float* scb = (const float*)d_in[11];
    const float* tiw = (const float*)d_in[12]; const float* tib = (const float*)d_in[13];

    float* out = (float*)d_out;          // transformed: 9216*1*32*32 floats
    float* aff = out + 9216 * 1024;      // aff: 9216*2*3 floats

    k_conv1<<<dim3(6, 192, 2), 128>>>(img, w1);
    k_redfb<<<dim3(16, 8), 256>>>(0);
    k_conv2<<<dim3(12, 48), 256>>>(w2);
    k_redfb<<<dim3(32, 8), 256>>>(1);
    k_conv3<<<dim3(12, 24, 2), 128>>>(w3);
    k_redfb<<<dim3(64, 1), 256>>>(2);
    k_heads<<<72, 128>>>(pw, pb, tw, tb, shw, shb, scw, scb, tiw, tib);
    k_sample<<<NPOS, 256>>>(img, out, aff);
}